// round 1
// baseline (speedup 1.0000x reference)
#include <cuda_runtime.h>
#include <cuda_bf16.h>
#include <math.h>

// GAT layer, fully collapsed:
//   s1 = h @ (W a1), s2 = h @ (W a2)                       [B,N]
//   m_i = leaky(s1_i + max_j s2_j)        (leaky monotone)
//   Z_i = e^{s1_i-m_i} * SUM_{s2_j > -s1_i} e^{s2_j}
//       + e^{.2 s1_i-m_i} * SUM_{s2_j <= -s1_i} e^{.2 s2_j}
//   c_j = e^{s2_j} * SUM_{s1_i > -s2_j} e^{s1_i-m_i}/Z_i
//       + e^{.2 s2_j} * SUM_{s1_i <= -s2_j} e^{.2 s1_i-m_i}/Z_i
//   out[b,:] = (1/N) * (c_b^T h_b) @ W
// All N^2 structure reduced to sort + prefix-sum + binary search.

#define B 8
#define N 2048
#define FIN 128
#define FOUT 64
#define ALPHA 0.2f

__device__ float d_u1[FIN];
__device__ float d_u2[FIN];
__device__ float d_s1[B * N];
__device__ float d_s2[B * N];
__device__ float d_c[B * N];
__device__ float d_v[B * FIN];

__device__ __forceinline__ float leaky(float x) { return x >= 0.f ? x : ALPHA * x; }

// ---------------- K1: u1 = W a1, u2 = W a2; zero d_v ----------------
__global__ void k_prep(const float* __restrict__ W, const float* __restrict__ a) {
    int t = threadIdx.x;            // 1024 threads
    d_v[t] = 0.f;                   // d_v has B*FIN = 1024 elements
    if (t < FIN) {
        float a1 = 0.f, a2 = 0.f;
#pragma unroll
        for (int f = 0; f < FOUT; f++) {
            float w = W[t * FOUT + f];
            a1 += w * a[f];
            a2 += w * a[FOUT + f];
        }
        d_u1[t] = a1;
        d_u2[t] = a2;
    }
}

// ---------------- K2: s1,s2 per (b,n) row; one warp per row ----------------
__global__ void k_scores(const float* __restrict__ h) {
    __shared__ float su1[FIN], su2[FIN];
    int tid = threadIdx.x;          // 256 threads = 8 warps
    if (tid < FIN) { su1[tid] = d_u1[tid]; su2[tid] = d_u2[tid]; }
    __syncthreads();
    int warp = tid >> 5, lane = tid & 31;
    int row = blockIdx.x * 8 + warp;                    // 0 .. B*N-1
    float4 hv = ((const float4*)h)[(size_t)row * (FIN / 4) + lane];
    int c = lane * 4;
    float a1 = hv.x * su1[c] + hv.y * su1[c + 1] + hv.z * su1[c + 2] + hv.w * su1[c + 3];
    float a2 = hv.x * su2[c] + hv.y * su2[c + 1] + hv.z * su2[c + 2] + hv.w * su2[c + 3];
#pragma unroll
    for (int o = 16; o; o >>= 1) {
        a1 += __shfl_xor_sync(0xffffffffu, a1, o);
        a2 += __shfl_xor_sync(0xffffffffu, a2, o);
    }
    if (lane == 0) { d_s1[row] = a1; d_s2[row] = a2; }
}

// ---------------- helpers for K3 ----------------
template <bool KV>
__device__ void bitonic2048(float* key, float* v1, float* v2, int tid) {
    for (int size = 2; size <= N; size <<= 1) {
        for (int stride = size >> 1; stride > 0; stride >>= 1) {
            __syncthreads();
#pragma unroll
            for (int r = 0; r < 2; r++) {
                int i = tid + (r << 10);
                int l = i ^ stride;
                if (l > i) {
                    bool up = ((i & size) == 0);
                    float ka = key[i], kb = key[l];
                    if ((ka > kb) == up) {
                        key[i] = kb; key[l] = ka;
                        if (KV) {
                            float t = v1[i]; v1[i] = v1[l]; v1[l] = t;
                            t = v2[i]; v2[i] = v2[l]; v2[l] = t;
                        }
                    }
                }
            }
        }
    }
    __syncthreads();
}

// In-place Blelloch exclusive scan of 2048 elements, 1024 threads.
// On exit: data[j] = sum_{t<j} in, *total = full sum.
__device__ void scan2048(float* data, float* total, int tid) {
    for (int d = 1; d < N; d <<= 1) {
        __syncthreads();
        int idx = (tid + 1) * (d << 1) - 1;
        if (idx < N) data[idx] += data[idx - d];
    }
    __syncthreads();
    if (tid == 0) { *total = data[N - 1]; data[N - 1] = 0.f; }
    for (int d = N >> 1; d >= 1; d >>= 1) {
        __syncthreads();
        int idx = (tid + 1) * (d << 1) - 1;
        if (idx < N) {
            float t = data[idx - d];
            data[idx - d] = data[idx];
            data[idx] += t;
        }
    }
    __syncthreads();
}

// count of key[j] <= t in sorted key[0..2047]
__device__ __forceinline__ int ubound2048(const float* key, float t) {
    int lo = 0, hi = N;
    while (lo < hi) {
        int m = (lo + hi) >> 1;
        if (key[m] <= t) lo = m + 1; else hi = m;
    }
    return lo;
}

// ---------------- K3: per-batch softmax column mass c[j] ----------------
__global__ void __launch_bounds__(1024, 1) k_attn() {
    int b = blockIdx.x;
    int tid = threadIdx.x;          // 1024

    __shared__ float s1o[N], s2o[N], key[N], v1[N], v2[N];
    __shared__ float totA, totB, smax;
    __shared__ float red[32];

    const float* gs1 = d_s1 + b * N;
    const float* gs2 = d_s2 + b * N;
#pragma unroll
    for (int r = 0; r < 2; r++) {
        int i = tid + (r << 10);
        s1o[i] = gs1[i];
        float s2 = gs2[i];
        s2o[i] = s2;
        key[i] = s2;
    }
    __syncthreads();

    // max of s2
    {
        float m = fmaxf(s2o[tid], s2o[tid + 1024]);
#pragma unroll
        for (int o = 16; o; o >>= 1) m = fmaxf(m, __shfl_xor_sync(0xffffffffu, m, o));
        if ((tid & 31) == 0) red[tid >> 5] = m;
        __syncthreads();
        if (tid == 0) {
            float mm = red[0];
            for (int w = 1; w < 32; w++) mm = fmaxf(mm, red[w]);
            smax = mm;
        }
        __syncthreads();
    }

    // sort s2 keys ascending
    bitonic2048<false>(key, v1, v2, tid);

    // v1 = exp(s2_sorted), v2 = exp(0.2*s2_sorted), then exclusive scans
#pragma unroll
    for (int r = 0; r < 2; r++) {
        int i = tid + (r << 10);
        float x = key[i];
        v1[i] = expf(x);
        v2[i] = expf(ALPHA * x);
    }
    scan2048(v1, &totA, tid);
    scan2048(v2, &totB, tid);

    // Z_i and g1,g2 per row i (kept in registers)
    float g1r[2], g2r[2];
    float sm = smax, tA = totA, tB = totB;
#pragma unroll
    for (int r = 0; r < 2; r++) {
        int i = tid + (r << 10);
        float s1 = s1o[i];
        float t = -s1;
        int cnt = ubound2048(key, t);
        float SA = (cnt < N) ? v1[cnt] : tA;   // sum e^{s2} over s2 <= t
        float SB = (cnt < N) ? v2[cnt] : tB;   // sum e^{.2 s2} over s2 <= t
        float Apos = tA - SA;                  // sum e^{s2} over s2 > t
        float m = leaky(s1 + sm);
        float e1 = expf(s1 - m);
        float e2 = expf(ALPHA * s1 - m);
        float Z = e1 * Apos + e2 * SB;
        float inv = 1.0f / Z;
        g1r[r] = e1 * inv;
        g2r[r] = e2 * inv;
    }
    __syncthreads();   // everyone done reading key/v1/v2 before reuse

    // re-key by s1, carry (g1,g2); sort + scan
#pragma unroll
    for (int r = 0; r < 2; r++) {
        int i = tid + (r << 10);
        key[i] = s1o[i];
        v1[i] = g1r[r];
        v2[i] = g2r[r];
    }
    bitonic2048<true>(key, v1, v2, tid);
    scan2048(v1, &totA, tid);   // reuse: totA = sum g1
    scan2048(v2, &totB, tid);   // totB = sum g2

    float tG1 = totA, tG2 = totB;
#pragma unroll
    for (int r = 0; r < 2; r++) {
        int j = tid + (r << 10);
        float s2 = s2o[j];
        float t = -s2;
        int cnt = ubound2048(key, t);
        float SG1 = (cnt < N) ? v1[cnt] : tG1;  // sum g1 over s1 <= t
        float SG2 = (cnt < N) ? v2[cnt] : tG2;  // sum g2 over s1 <= t
        float P = tG1 - SG1;                    // sum g1 over s1 > t
        float c = expf(s2) * P + expf(ALPHA * s2) * SG2;
        d_c[b * N + j] = c;
    }
}

// ---------------- K4: v[b,:] = sum_j c[b,j] * h[b,j,:] ----------------
__global__ void k_wsum(const float* __restrict__ h) {
    int b = blockIdx.x >> 6;              // 64 chunks per batch
    int chunk = blockIdx.x & 63;
    int k = threadIdx.x & 127;            // 256 threads: 2 row-groups x 128 dims
    int half = threadIdx.x >> 7;
    const float* hb = h + (size_t)b * N * FIN;
    const float* cb = d_c + b * N;
    int j0 = chunk * 32 + half * 16;
    float acc = 0.f;
#pragma unroll 4
    for (int j = j0; j < j0 + 16; j++)
        acc += cb[j] * hb[(size_t)j * FIN + k];
    atomicAdd(&d_v[b * FIN + k], acc);
}

// ---------------- K5: out[b,f] = (1/N) * v[b,:] . W[:,f] ----------------
__global__ void k_out(const float* __restrict__ W, float* __restrict__ out) {
    int idx = threadIdx.x;                // 512 = B*FOUT
    int b = idx >> 6, f = idx & 63;
    float acc = 0.f;
#pragma unroll
    for (int k = 0; k < FIN; k++) acc += d_v[b * FIN + k] * W[k * FOUT + f];
    out[idx] = acc * (1.0f / (float)N);
}

extern "C" void kernel_launch(void* const* d_in, const int* in_sizes, int n_in,
                              void* d_out, int out_size) {
    (void)in_sizes; (void)n_in; (void)out_size;
    const float* h = (const float*)d_in[0];
    const float* W = (const float*)d_in[1];
    const float* a = (const float*)d_in[2];
    float* out = (float*)d_out;

    k_prep<<<1, 1024>>>(W, a);
    k_scores<<<(B * N) / 8, 256>>>(h);
    k_attn<<<B, 1024>>>();
    k_wsum<<<B * 64, 256>>>(h);
    k_out<<<1, 512>>>(W, out);
}

// round 3
// speedup vs baseline: 2.5528x; 2.5528x over previous
#include <cuda_runtime.h>
#include <cuda_bf16.h>
#include <math.h>

// GAT layer, fully collapsed (see round 1), with the sort replaced by a
// bucket/prefix structure:
//   - keys binned into NB=1024 value-range bins (monotone fp map)
//   - per-bin sums of the needed exponentials, exclusive-scanned
//   - each threshold query = bin prefix + exact compares in the boundary bin
// Branch selection (s2_j <= -s1_i) is decided by exact fp compares, matching
// the reference's sign(fl(s1+s2)) branch.

#define B 8
#define N 2048
#define FIN 128
#define FOUT 64
#define ALPHA 0.2f
#define NB 1024

__device__ float d_u1[FIN];
__device__ float d_u2[FIN];
__device__ float d_s1[B * N];
__device__ float d_s2[B * N];
__device__ float d_c[B * N];
__device__ float d_v[B * FIN];

__device__ __forceinline__ float leaky(float x) { return x >= 0.f ? x : ALPHA * x; }

__device__ __forceinline__ int binOf(float x, float lo, float scale) {
    float f = (x - lo) * scale;
    f = fminf(fmaxf(f, 0.f), (float)(NB - 1));
    return (int)f;
}

// ---------------- K1: u1 = W a1, u2 = W a2; zero d_v ----------------
__global__ void k_prep(const float* __restrict__ W, const float* __restrict__ a) {
    int t = threadIdx.x;            // 1024 threads
    d_v[t] = 0.f;                   // B*FIN = 1024
    if (t < FIN) {
        float a1 = 0.f, a2 = 0.f;
#pragma unroll
        for (int f = 0; f < FOUT; f++) {
            float w = W[t * FOUT + f];
            a1 += w * a[f];
            a2 += w * a[FOUT + f];
        }
        d_u1[t] = a1;
        d_u2[t] = a2;
    }
}

// ---------------- K2: s1,s2 per (b,n) row; one warp per row ----------------
__global__ void k_scores(const float* __restrict__ h) {
    __shared__ float su1[FIN], su2[FIN];
    int tid = threadIdx.x;          // 256 threads = 8 warps
    if (tid < FIN) { su1[tid] = d_u1[tid]; su2[tid] = d_u2[tid]; }
    __syncthreads();
    int warp = tid >> 5, lane = tid & 31;
    int row = blockIdx.x * 8 + warp;
    float4 hv = ((const float4*)h)[(size_t)row * (FIN / 4) + lane];
    int c = lane * 4;
    float a1 = hv.x * su1[c] + hv.y * su1[c + 1] + hv.z * su1[c + 2] + hv.w * su1[c + 3];
    float a2 = hv.x * su2[c] + hv.y * su2[c + 1] + hv.z * su2[c + 2] + hv.w * su2[c + 3];
#pragma unroll
    for (int o = 16; o; o >>= 1) {
        a1 += __shfl_xor_sync(0xffffffffu, a1, o);
        a2 += __shfl_xor_sync(0xffffffffu, a2, o);
    }
    if (lane == 0) { d_s1[row] = a1; d_s2[row] = a2; }
}

// ---------------- K3: per-batch softmax column mass c[j] ----------------
__global__ void __launch_bounds__(1024, 1) k_attn() {
    int b = blockIdx.x;
    int tid = threadIdx.x;          // 1024
    int lane = tid & 31, wid = tid >> 5;

    __shared__ float val[N], pA[N], pB[N];       // element data in bin order
    __shared__ float binA[NB], binB[NB];         // per-bin sums -> excl prefix
    __shared__ int   off[NB + 1];                // bin start offsets
    __shared__ int   cursor[NB];                 // hist counts -> scatter cursors
    __shared__ int   sI[32];
    __shared__ float sA[32], sB[32];
    __shared__ float bc[8];                      // lo2,hi2,lo1,hi1,totA,totB

    // --- load s1,s2 into registers (thread owns i = tid and tid+1024) ---
    float rs1[2], rs2[2];
    {
        const float* gs1 = d_s1 + b * N;
        const float* gs2 = d_s2 + b * N;
#pragma unroll
        for (int r = 0; r < 2; r++) {
            int i = tid + (r << 10);
            rs1[r] = gs1[i];
            rs2[r] = gs2[i];
        }
    }

    // --- min/max of s1 and s2 (for bin ranges; max2 is also the softmax max) ---
    {
        float l1 = fminf(rs1[0], rs1[1]), h1 = fmaxf(rs1[0], rs1[1]);
        float l2 = fminf(rs2[0], rs2[1]), h2 = fmaxf(rs2[0], rs2[1]);
#pragma unroll
        for (int o = 16; o; o >>= 1) {
            l1 = fminf(l1, __shfl_xor_sync(0xffffffffu, l1, o));
            h1 = fmaxf(h1, __shfl_xor_sync(0xffffffffu, h1, o));
            l2 = fminf(l2, __shfl_xor_sync(0xffffffffu, l2, o));
            h2 = fmaxf(h2, __shfl_xor_sync(0xffffffffu, h2, o));
        }
        if (lane == 0) {
            val[wid] = l1; val[32 + wid] = h1; val[64 + wid] = l2; val[96 + wid] = h2;
        }
        __syncthreads();
        if (tid == 0) {
            float a0 = val[0], a1m = val[32], a2m = val[64], a3 = val[96];
            for (int w = 1; w < 32; w++) {
                a0 = fminf(a0, val[w]);
                a1m = fmaxf(a1m, val[32 + w]);
                a2m = fminf(a2m, val[64 + w]);
                a3 = fmaxf(a3, val[96 + w]);
            }
            bc[0] = a2m; bc[1] = a3;   // lo2, hi2
            bc[2] = a0;  bc[3] = a1m;  // lo1, hi1
        }
        __syncthreads();
    }

    // ================= PASS 1: key = s2, sums of e^{s2}, e^{.2 s2} ==========
    float lo2 = bc[0], hi2 = bc[1];
    float scale2 = (hi2 > lo2) ? ((float)NB / (hi2 - lo2)) : 0.f;

    cursor[tid] = 0; binA[tid] = 0.f; binB[tid] = 0.f;
    __syncthreads();

    float eA[2], eB[2]; int bn[2];
#pragma unroll
    for (int r = 0; r < 2; r++) {
        float x = rs2[r];
        eA[r] = expf(x);
        eB[r] = expf(ALPHA * x);
        int bi = binOf(x, lo2, scale2);
        bn[r] = bi;
        atomicAdd(&cursor[bi], 1);
        atomicAdd(&binA[bi], eA[r]);
        atomicAdd(&binB[bi], eB[r]);
    }
    __syncthreads();

    // combined exclusive scan over 1024 bins: (count, sumA, sumB)
    {
        int c = cursor[tid]; float a = binA[tid], bb = binB[tid];
        int ci = c; float ai = a, bi2 = bb;
#pragma unroll
        for (int o = 1; o < 32; o <<= 1) {
            int cy = __shfl_up_sync(0xffffffffu, ci, o);
            float ay = __shfl_up_sync(0xffffffffu, ai, o);
            float by = __shfl_up_sync(0xffffffffu, bi2, o);
            if (lane >= o) { ci += cy; ai += ay; bi2 += by; }
        }
        if (lane == 31) { sI[wid] = ci; sA[wid] = ai; sB[wid] = bi2; }
        __syncthreads();
        if (wid == 0) {
            int cw = sI[lane]; float aw = sA[lane], bw = sB[lane];
            int cwi = cw; float awi = aw, bwi = bw;
#pragma unroll
            for (int o = 1; o < 32; o <<= 1) {
                int cy = __shfl_up_sync(0xffffffffu, cwi, o);
                float ay = __shfl_up_sync(0xffffffffu, awi, o);
                float by = __shfl_up_sync(0xffffffffu, bwi, o);
                if (lane >= o) { cwi += cy; awi += ay; bwi += by; }
            }
            sI[lane] = cwi - cw; sA[lane] = awi - aw; sB[lane] = bwi - bw;
            if (lane == 31) { bc[4] = awi; bc[5] = bwi; }
        }
        __syncthreads();
        int cex = ci - c + sI[wid];
        float aex = ai - a + sA[wid];
        float bex = bi2 - bb + sB[wid];
        off[tid] = cex; cursor[tid] = cex;
        binA[tid] = aex; binB[tid] = bex;
        if (tid == 0) off[NB] = N;
    }
    __syncthreads();

    // scatter into bin order
#pragma unroll
    for (int r = 0; r < 2; r++) {
        int p = atomicAdd(&cursor[bn[r]], 1);
        val[p] = rs2[r]; pA[p] = eA[r]; pB[p] = eB[r];
    }
    __syncthreads();

    // queries: Z_i and g1,g2 per row i
    float g1[2], g2[2];
    {
        float smax = bc[1], tA = bc[4], tB = bc[5];
#pragma unroll
        for (int r = 0; r < 2; r++) {
            float s1 = rs1[r];
            float t = -s1;
            int qb = binOf(t, lo2, scale2);
            float SA = binA[qb], SB = binB[qb];
            int pe = off[qb + 1];
            for (int p = off[qb]; p < pe; p++) {
                if (val[p] <= t) { SA += pA[p]; SB += pB[p]; }
            }
            float Apos = tA - SA;               // sum e^{s2} over s2 > -s1
            float m = leaky(s1 + smax);
            float e1 = expf(s1 - m);
            float e2 = expf(ALPHA * s1 - m);
            float inv = 1.0f / (e1 * Apos + e2 * SB);
            g1[r] = e1 * inv;
            g2[r] = e2 * inv;
        }
    }
    __syncthreads();

    // ================= PASS 2: key = s1, payload (g1,g2) ====================
    float lo1 = bc[2], hi1 = bc[3];
    float scale1 = (hi1 > lo1) ? ((float)NB / (hi1 - lo1)) : 0.f;

    cursor[tid] = 0; binA[tid] = 0.f; binB[tid] = 0.f;
    __syncthreads();

#pragma unroll
    for (int r = 0; r < 2; r++) {
        int bi = binOf(rs1[r], lo1, scale1);
        bn[r] = bi;
        atomicAdd(&cursor[bi], 1);
        atomicAdd(&binA[bi], g1[r]);
        atomicAdd(&binB[bi], g2[r]);
    }
    __syncthreads();

    {
        int c = cursor[tid]; float a = binA[tid], bb = binB[tid];
        int ci = c; float ai = a, bi2 = bb;
#pragma unroll
        for (int o = 1; o < 32; o <<= 1) {
            int cy = __shfl_up_sync(0xffffffffu, ci, o);
            float ay = __shfl_up_sync(0xffffffffu, ai, o);
            float by = __shfl_up_sync(0xffffffffu, bi2, o);
            if (lane >= o) { ci += cy; ai += ay; bi2 += by; }
        }
        if (lane == 31) { sI[wid] = ci; sA[wid] = ai; sB[wid] = bi2; }
        __syncthreads();
        if (wid == 0) {
            int cw = sI[lane]; float aw = sA[lane], bw = sB[lane];
            int cwi = cw; float awi = aw, bwi = bw;
#pragma unroll
            for (int o = 1; o < 32; o <<= 1) {
                int cy = __shfl_up_sync(0xffffffffu, cwi, o);
                float ay = __shfl_up_sync(0xffffffffu, awi, o);
                float by = __shfl_up_sync(0xffffffffu, bwi, o);
                if (lane >= o) { cwi += cy; awi += ay; bwi += by; }
            }
            sI[lane] = cwi - cw; sA[lane] = awi - aw; sB[lane] = bwi - bw;
            if (lane == 31) { bc[4] = awi; bc[5] = bwi; }
        }
        __syncthreads();
        int cex = ci - c + sI[wid];
        float aex = ai - a + sA[wid];
        float bex = bi2 - bb + sB[wid];
        off[tid] = cex; cursor[tid] = cex;
        binA[tid] = aex; binB[tid] = bex;
        if (tid == 0) off[NB] = N;
    }
    __syncthreads();

#pragma unroll
    for (int r = 0; r < 2; r++) {
        int p = atomicAdd(&cursor[bn[r]], 1);
        val[p] = rs1[r]; pA[p] = g1[r]; pB[p] = g2[r];
    }
    __syncthreads();

    // queries: column mass c_j
    {
        float tG1 = bc[4], tG2 = bc[5];
#pragma unroll
        for (int r = 0; r < 2; r++) {
            int j = tid + (r << 10);
            float s2 = rs2[r];
            float t = -s2;
            int qb = binOf(t, lo1, scale1);
            float SG1 = binA[qb], SG2 = binB[qb];
            int pe = off[qb + 1];
            for (int p = off[qb]; p < pe; p++) {
                if (val[p] <= t) { SG1 += pA[p]; SG2 += pB[p]; }
            }
            float P = tG1 - SG1;                // sum g1 over s1 > -s2
            float c = expf(s2) * P + expf(ALPHA * s2) * SG2;
            d_c[b * N + j] = c;
        }
    }
}

// ---------------- K4: v[b,:] = sum_j c[b,j] * h[b,j,:] ----------------
// warp-per-row, float4 loads, block-level smem reduce, then 128 atomics/block
__global__ void k_wsum(const float* __restrict__ h) {
    __shared__ float red[8 * FIN];
    int b = blockIdx.x >> 5;              // grid = B*32
    int chunk = blockIdx.x & 31;
    int wid = threadIdx.x >> 5, lane = threadIdx.x & 31;   // 256 threads
    const float4* h4 = (const float4*)h;
    const float* cb = d_c + b * N;
    size_t base = (size_t)b * N * (FIN / 4);
    int j0 = chunk * 64 + wid * 8;
    float4 acc = make_float4(0.f, 0.f, 0.f, 0.f);
#pragma unroll
    for (int q = 0; q < 8; q++) {
        int j = j0 + q;
        float cj = cb[j];
        float4 hv = h4[base + (size_t)j * (FIN / 4) + lane];
        acc.x = fmaf(cj, hv.x, acc.x);
        acc.y = fmaf(cj, hv.y, acc.y);
        acc.z = fmaf(cj, hv.z, acc.z);
        acc.w = fmaf(cj, hv.w, acc.w);
    }
    ((float4*)red)[wid * 32 + lane] = acc;
    __syncthreads();
    if (threadIdx.x < FIN) {
        int k = threadIdx.x;
        float s = 0.f;
#pragma unroll
        for (int w = 0; w < 8; w++) s += red[w * FIN + k];
        atomicAdd(&d_v[b * FIN + k], s);
    }
}

// ---------------- K5: out[b,f] = (1/N) * v[b,:] . W[:,f] ----------------
__global__ void k_out(const float* __restrict__ W, float* __restrict__ out) {
    int idx = threadIdx.x;                // 512 = B*FOUT
    int b = idx >> 6, f = idx & 63;
    float acc = 0.f;
#pragma unroll
    for (int k = 0; k < FIN; k++) acc += d_v[b * FIN + k] * W[k * FOUT + f];
    out[idx] = acc * (1.0f / (float)N);
}

extern "C" void kernel_launch(void* const* d_in, const int* in_sizes, int n_in,
                              void* d_out, int out_size) {
    (void)in_sizes; (void)n_in; (void)out_size;
    const float* h = (const float*)d_in[0];
    const float* W = (const float*)d_in[1];
    const float* a = (const float*)d_in[2];
    float* out = (float*)d_out;

    k_prep<<<1, 1024>>>(W, a);
    k_scores<<<(B * N) / 8, 256>>>(h);
    k_attn<<<B, 1024>>>();
    k_wsum<<<B * 32, 256>>>(h);
    k_out<<<1, 512>>>(W, out);
}